// round 9
// baseline (speedup 1.0000x reference)
#include <cuda_runtime.h>
#include <cuda_fp16.h>
#include <cstdint>

// ===========================================================================
// TensorTrainProjection via dense operator + single fp16 tensor-core GEMM.
//   W[d,j] = TT-contraction of 9 cores (2048 x 2048), sigma(W) ~ 2^16
//   out = X @ W,  X: [8192, 2048] fp32
// fp16 GEMM (K=2048), W stored * 2^-8 (exact), epilogue * 256.
// Round-9: fused pre-work (conv_X + chain12 + build_R in ONE kernel),
// evict-first (__stcs) epilogue stores to preserve L2-resident operands.
// 4 launches; GEMM is index 3 (the one ncu captures).
// ===========================================================================

__device__ __forceinline__ uint32_t smem_u32(const void* p) {
    uint32_t a;
    asm("{ .reg .u64 t; cvta.to.shared.u64 t, %1; cvt.u32.u64 %0, t; }" : "=r"(a) : "l"(p));
    return a;
}
__device__ __forceinline__ uint32_t swz(uint32_t o) { return o ^ ((o >> 3) & 0x70); }

__device__ __forceinline__ uint32_t h2u(__half2 v) {
    return (uint32_t)__half_as_ushort(__low2half(v)) |
           ((uint32_t)__half_as_ushort(__high2half(v)) << 16);
}
__device__ __forceinline__ uint32_t pack2h(__half a, __half b) {
    return (uint32_t)__half_as_ushort(a) | ((uint32_t)__half_as_ushort(b) << 16);
}

__device__ __forceinline__ void cp16(uint32_t dst, const void* src) {
    asm volatile("cp.async.cg.shared.global [%0], [%1], 16;" :: "r"(dst), "l"(src) : "memory");
}
__device__ __forceinline__ void cp_commit() { asm volatile("cp.async.commit_group;" ::: "memory"); }
template <int N>
__device__ __forceinline__ void cp_wait() { asm volatile("cp.async.wait_group %0;" :: "n"(N) : "memory"); }

__device__ __forceinline__ void ldsm_x4(uint32_t* r, uint32_t addr) {
    asm volatile("ldmatrix.sync.aligned.m8n8.x4.shared.b16 {%0,%1,%2,%3}, [%4];"
                 : "=r"(r[0]), "=r"(r[1]), "=r"(r[2]), "=r"(r[3]) : "r"(addr));
}
__device__ __forceinline__ void mma16816f16(float* c, const uint32_t* a, const uint32_t* b) {
    asm volatile(
        "mma.sync.aligned.m16n8k16.row.col.f32.f16.f16.f32 "
        "{%0,%1,%2,%3}, {%4,%5,%6,%7}, {%8,%9}, {%0,%1,%2,%3};"
        : "+f"(c[0]), "+f"(c[1]), "+f"(c[2]), "+f"(c[3])
        : "r"(a[0]), "r"(a[1]), "r"(a[2]), "r"(a[3]), "r"(b[0]), "r"(b[1]));
}

// ---------------- scratch (static __device__, no allocs) --------------------
static __device__ __align__(16) unsigned char g_Xh[33554432];  // 64 mt * 32 ch * 16KB
static __device__ __align__(16) unsigned char g_Wh[8388608];   // 16 nt * 32 ch * 16KB
static __device__ float g_S2[16384];                           // [32][32][16]
static __device__ float g_R[4096];                             // [16][16][16]
static __device__ float g_Ls[262144];                          // [128 jh][2048]

// ---------------- launch 0: fused pre (conv_X | chain12 | build_R) ----------
// blocks 0..8191: X -> fp16 pre-swizzled tiles
// block 8192: cores 0-2 -> S2[32][32][16]
// block 8193: cores 8,7,6,5 -> R  (core7 bond-swapped)
__global__ void mega_pre(const float* __restrict__ x, unsigned char* __restrict__ Xh,
                         const float* __restrict__ p0, const float* __restrict__ p1,
                         const float* __restrict__ p2,
                         const float* __restrict__ p5, const float* __restrict__ p6,
                         const float* __restrict__ p7, const float* __restrict__ p8,
                         float* __restrict__ S2out, float* __restrict__ Rout)
{
    __shared__ float buf[8192];
    int b = blockIdx.x, t = threadIdx.x;

    if (b < 8192) {
        // ---- conv_X ----
        int idx = b * 256 + t;
        int m = idx >> 8;
        int k0 = (idx & 255) * 8;
        const float* row = x + (size_t)m * 2048 + k0;
        float4 v0 = *(const float4*)row;
        float4 v1 = *(const float4*)(row + 4);
        uint32_t off = (uint32_t)(((m >> 7) * 32 + (k0 >> 6)) << 14) + swz((m & 127) * 128 + (k0 & 63) * 2);
        uint4 pk;
        pk.x = h2u(__floats2half2_rn(v0.x, v0.y));
        pk.y = h2u(__floats2half2_rn(v0.z, v0.w));
        pk.z = h2u(__floats2half2_rn(v1.x, v1.y));
        pk.w = h2u(__floats2half2_rn(v1.z, v1.w));
        *(uint4*)(Xh + off) = pk;
        return;
    }

    if (b == 8192) {
        // ---- chain12 (verified): s0 = buf[0..1023], c = buf[1024..2047], s1 = buf[2048..6143]
        float* s0 = buf;
        float* c  = buf + 1024;
        float* s1 = buf + 2048;
        for (int i = t; i < 1024; i += 256) { s0[i] = p0[i]; c[i] = p1[i]; }
        __syncthreads();
        for (int idx = t; idx < 256; idx += 256) {
            int bb = idx & 1, j = (idx >> 1) & 7, a = (idx >> 4) & 1, d = idx >> 5;
            const float* sr = s0 + (d * 8 + j) * 16;
            int ab = a * 2 + bb;
            float* o = s1 + ((d * 2 + a) * 16 + (j * 2 + bb)) * 16;
            #pragma unroll
            for (int r = 0; r < 16; ++r) {
                float acc = 0.f;
                #pragma unroll
                for (int l = 0; l < 16; ++l) acc = fmaf(sr[l], c[(ab * 16 + l) * 16 + r], acc);
                o[r] = acc;
            }
        }
        __syncthreads();
        for (int i = t; i < 1024; i += 256) c[i] = p2[i];
        __syncthreads();
        for (int idx = t; idx < 1024; idx += 256) {
            int bb = idx & 1, j = (idx >> 1) & 15, a = (idx >> 5) & 1, d = idx >> 6;
            const float* sr = s1 + (d * 16 + j) * 16;
            int ab = a * 2 + bb;
            float* o = S2out + ((d * 2 + a) * 32 + (j * 2 + bb)) * 16;
            #pragma unroll
            for (int r = 0; r < 16; ++r) {
                float acc = 0.f;
                #pragma unroll
                for (int l = 0; l < 16; ++l) acc = fmaf(sr[l], c[(ab * 16 + l) * 16 + r], acc);
                o[r] = acc;
            }
        }
        return;
    }

    // ---- build_R (verified): S = buf[0..4095], T = buf[4096..8191]
    float* S = buf;
    float* T = buf + 4096;
    if (t < 64) { int l = t >> 2, d = (t >> 1) & 1, jj = t & 1; S[l * 4 + d * 2 + jj] = p8[(d * 2 + jj) * 16 + l]; }
    __syncthreads();
    if (t < 256) {  // core 7: G[a,b,l,r] = p7[a][b][r][l]
        int l = t >> 4, dp = (t >> 2) & 3, jp = t & 3;
        int a = dp >> 1, d = dp & 1, bb = jp >> 1, jj = jp & 1;
        float acc = 0.f;
        #pragma unroll
        for (int r = 0; r < 16; ++r) acc = fmaf(p7[((a * 2 + bb) * 16 + r) * 16 + l], S[r * 4 + d * 2 + jj], acc);
        T[l * 16 + dp * 4 + jp] = acc;
    }
    __syncthreads();
    for (int i = t; i < 1024; i += 256) {  // core 6
        int l = i >> 6, dp = (i >> 3) & 7, jp = i & 7;
        int a = dp >> 2, d = dp & 3, bb = jp >> 2, jj = jp & 3;
        float acc = 0.f;
        #pragma unroll
        for (int r = 0; r < 16; ++r) acc = fmaf(p6[((a * 2 + bb) * 16 + l) * 16 + r], T[r * 16 + d * 4 + jj], acc);
        S[l * 64 + dp * 8 + jp] = acc;
    }
    __syncthreads();
    for (int i = t; i < 4096; i += 256) {  // core 5 -> R[l*256 + dl*16 + jl]
        int l = i >> 8, dp = (i >> 4) & 15, jp = i & 15;
        int a = dp >> 3, d = dp & 7, bb = jp >> 3, jj = jp & 7;
        float acc = 0.f;
        #pragma unroll
        for (int r = 0; r < 16; ++r) acc = fmaf(p5[((a * 2 + bb) * 16 + l) * 16 + r], S[r * 64 + d * 8 + jj], acc);
        Rout[i] = acc;
    }
}

// ---------------- launch 1: Ls[jh][dh*16+r] via cores 3,4 (128 blocks) -------
__global__ void build_Ls(const float* __restrict__ S2,
                         const float* __restrict__ p3, const float* __restrict__ p4,
                         float* __restrict__ Lsg)
{
    __shared__ float S[3584];
    int t = threadIdx.x, jh = blockIdx.x;
    for (int i = t; i < 512; i += 256) {
        int d2 = i >> 4, l = i & 15;
        S[i] = S2[((d2 * 32) + (jh >> 2)) * 16 + l];
    }
    for (int i = t; i < 1024; i += 256) { S[512 + i] = p3[i]; S[2560 + i] = p4[i]; }
    __syncthreads();
    for (int i = t; i < 1024; i += 256) {   // core 3: T3[d3*16+r]
        int d3 = i >> 4, r = i & 15;
        int a = d3 & 1, b3 = (jh >> 1) & 1, d2 = d3 >> 1;
        float acc = 0.f;
        #pragma unroll
        for (int l = 0; l < 16; ++l)
            acc = fmaf(S[d2 * 16 + l], S[512 + ((a * 2 + b3) * 16 + l) * 16 + r], acc);
        S[1536 + i] = acc;
    }
    __syncthreads();
    float* o = Lsg + (size_t)jh * 2048;
    for (int i = t; i < 2048; i += 256) {   // core 4: Ls[dh*16+r]
        int dh = i >> 4, r = i & 15;
        int a = dh & 1, b4 = jh & 1, d3 = dh >> 1;
        float acc = 0.f;
        #pragma unroll
        for (int l = 0; l < 16; ++l)
            acc = fmaf(S[1536 + d3 * 16 + l], S[2560 + ((a * 2 + b4) * 16 + l) * 16 + r], acc);
        o[i] = acc;
    }
}

// ---------------- launch 2: combine -> Wh (fp16 * 2^-8, pre-swizzled) --------
__global__ void combine_W(const float* __restrict__ Lsg, const float* __restrict__ Rg,
                          unsigned char* __restrict__ Wh)
{
    __shared__ float ls[2048], rr[256];
    int t = threadIdx.x, j = blockIdx.x;
    int jh = j >> 4, jl = j & 15;
    const float* lsrc = Lsg + (size_t)jh * 2048;
    for (int i = t; i < 2048; i += 256) ls[i] = lsrc[i];
    { int r = t >> 4, dl = t & 15; rr[t] = Rg[r * 256 + dl * 16 + jl]; }
    __syncthreads();

    __half h[8];
    int dh = t >> 1;
    const float* lrow = ls + dh * 16;
    #pragma unroll
    for (int i = 0; i < 8; ++i) {
        int dl = (t & 1) * 8 + i;
        float acc = 0.f;
        #pragma unroll
        for (int r = 0; r < 16; ++r)
            acc = fmaf(lrow[r], rr[r * 16 + dl], acc);
        h[i] = __float2half_rn(acc * 0.00390625f);   // * 2^-8 exact
    }
    uint4 pk;
    pk.x = pack2h(h[0], h[1]);
    pk.y = pack2h(h[2], h[3]);
    pk.z = pack2h(h[4], h[5]);
    pk.w = pack2h(h[6], h[7]);
    uint32_t off = (uint32_t)(((j >> 7) * 32 + ((t * 8) >> 6)) << 14) + swz((j & 127) * 128 + ((t * 8) & 63) * 2);
    *(uint4*)(Wh + off) = pk;
}

// ---------------- launch 3: persistent fp16 GEMM -----------------------------
// 296 CTAs (2/SM; CTA i and i+148 share an SM -> 7 or 6 tiles per SM, balanced)
// cp.async 3-stage ring runs continuously across tile boundaries.
// Epilogue uses __stcs (evict-first) to keep Xh/Wh L2-resident.
static constexpr int STAGE_BYTES = 32768;
static constexpr uint32_t GEMM_SMEM = 3 * STAGE_BYTES;

__global__ void __launch_bounds__(256, 2)
tt_gemm_f16(const unsigned char* __restrict__ Xh, const unsigned char* __restrict__ Wh,
            float* __restrict__ out)
{
    extern __shared__ unsigned char smem[];
    uint32_t sb = smem_u32(smem);
    int tid = threadIdx.x, wid = tid >> 5, lane = tid & 31;
    int cta = blockIdx.x;                          // 0..295
    int ntiles = (cta < 136) ? 4 : 3;              // 136*4 + 160*3 = 1024 tiles
    int total_it = ntiles << 5;                    // 32 k-chunks per tile

    int wm = (wid & 1) * 64;
    int wn = (wid >> 1) * 32;
    int arow = wm + (lane & 15);
    int akb  = (lane >> 4) * 16;
    int brow4 = wn + ((lane >> 4) & 1) * 8 + (lane & 7);
    int bkb   = ((lane >> 3) & 1) * 16;

    float acc[4][4][4];
    #pragma unroll
    for (int mi = 0; mi < 4; ++mi)
        #pragma unroll
        for (int ni = 0; ni < 4; ++ni)
            #pragma unroll
            for (int q = 0; q < 4; ++q) acc[mi][ni][q] = 0.f;

    auto issue = [&](int it2) {
        int ti = it2 >> 5, ck = it2 & 31;
        int tt = cta + 296 * ti;
        int by = tt >> 4, bx = tt & 15;
        const unsigned char* as = Xh + (((size_t)by * 32 + ck) << 14) + tid * 16;
        const unsigned char* bs = Wh + (((size_t)bx * 32 + ck) << 14) + tid * 16;
        uint32_t dst = sb + (uint32_t)(it2 % 3) * STAGE_BYTES + tid * 16;
        #pragma unroll
        for (int i = 0; i < 4; ++i) cp16(dst + i * 4096, as + i * 4096);
        #pragma unroll
        for (int i = 0; i < 4; ++i) cp16(dst + 16384 + i * 4096, bs + i * 4096);
    };

    issue(0); cp_commit();
    issue(1); cp_commit();

    for (int it = 0; it < total_it; ++it) {
        cp_wait<1>();
        __syncthreads();
        if (it + 2 < total_it) issue(it + 2);
        cp_commit();

        uint32_t base = sb + (uint32_t)(it % 3) * STAGE_BYTES;
        #pragma unroll
        for (int ks = 0; ks < 4; ++ks) {
            uint32_t af[4][4], bf[4][2];
            #pragma unroll
            for (int mi = 0; mi < 4; ++mi)
                ldsm_x4(af[mi], base + swz((uint32_t)((arow + mi * 16) * 128 + ks * 32 + akb)));
            #pragma unroll
            for (int blk = 0; blk < 2; ++blk) {
                uint32_t tmp[4];
                ldsm_x4(tmp, base + 16384 + swz((uint32_t)((brow4 + blk * 16) * 128 + ks * 32 + bkb)));
                bf[2 * blk][0] = tmp[0]; bf[2 * blk][1] = tmp[1];
                bf[2 * blk + 1][0] = tmp[2]; bf[2 * blk + 1][1] = tmp[3];
            }
            #pragma unroll
            for (int mi = 0; mi < 4; ++mi)
                #pragma unroll
                for (int ni = 0; ni < 4; ++ni)
                    mma16816f16(acc[mi][ni], af[mi], bf[ni]);
        }

        if ((it & 31) == 31) {
            int tt = cta + 296 * (it >> 5);
            int by = tt >> 4, bx = tt & 15;
            int m0 = by * 128 + wm + (lane >> 2);
            int n0 = bx * 128 + wn + (lane & 3) * 2;
            #pragma unroll
            for (int mi = 0; mi < 4; ++mi) {
                #pragma unroll
                for (int ni = 0; ni < 4; ++ni) {
                    float* pp = out + (size_t)(m0 + mi * 16) * 2048 + n0 + ni * 8;
                    __stcs((float2*)pp,
                           make_float2(acc[mi][ni][0] * 256.f, acc[mi][ni][1] * 256.f));
                    __stcs((float2*)(pp + 8 * 2048),
                           make_float2(acc[mi][ni][2] * 256.f, acc[mi][ni][3] * 256.f));
                    #pragma unroll
                    for (int q = 0; q < 4; ++q) acc[mi][ni][q] = 0.f;
                }
            }
        }
    }
}

// ---------------- launch ------------------------------------------------------
extern "C" void kernel_launch(void* const* d_in, const int* in_sizes, int n_in,
                              void* d_out, int out_size)
{
    (void)in_sizes; (void)n_in; (void)out_size;
    const float* x = (const float*)d_in[0];
    const float* p[9];
    for (int i = 0; i < 9; ++i) p[i] = (const float*)d_in[1 + i];

    unsigned char *Xh, *Wh;
    float *S2, *R, *Ls;
    cudaGetSymbolAddress((void**)&Xh, g_Xh);
    cudaGetSymbolAddress((void**)&Wh, g_Wh);
    cudaGetSymbolAddress((void**)&S2, g_S2);
    cudaGetSymbolAddress((void**)&R, g_R);
    cudaGetSymbolAddress((void**)&Ls, g_Ls);

    mega_pre<<<8194, 256>>>(x, Xh, p[0], p[1], p[2], p[5], p[6], p[7], p[8], S2, R);  // 0
    build_Ls<<<128, 256>>>(S2, p[3], p[4], Ls);                                        // 1
    combine_W<<<2048, 256>>>(Ls, R, Wh);                                               // 2
    cudaFuncSetAttribute(tt_gemm_f16, cudaFuncAttributeMaxDynamicSharedMemorySize, GEMM_SMEM);
    tt_gemm_f16<<<296, 256, GEMM_SMEM>>>(Xh, Wh, (float*)d_out);                       // 3
}